// round 13
// baseline (speedup 1.0000x reference)
#include <cuda_runtime.h>
#include <cuda_bf16.h>

#define NB 8
#define NT 16384
#define NH 512
#define NC 24
#define NK 100
#define RST 264            // ring stride in floats (256 live + 8 pad)
#define FULL 0xffffffffu

// Scratch (device globals; no allocation allowed)
__device__ float g_scores[NB * NC * NT];        // [b][c][t]
__device__ float g_cum[NB * NC * (NT + 1)];     // [b][c][t], cum[0]=0

// ---------------------------------------------------------------------------
// Kernel 1: scores[b,t,c] = hidden[b,t,:] @ W[:,c] + bias[c], written [b][c][t]
// ---------------------------------------------------------------------------
__global__ __launch_bounds__(256) void gemm_kernel(const float* __restrict__ hs,
                                                   const float* __restrict__ W,
                                                   const float* __restrict__ bias) {
    __shared__ __align__(16) float Wsm[256 * NC];   // 24 KB
    __shared__ float bsm[NC];
    const int tid = threadIdx.x;
    const int row = blockIdx.x * 256 + tid;         // row = b*NT + t
    if (tid < NC) bsm[tid] = bias[tid];

    float acc[NC];
#pragma unroll
    for (int c = 0; c < NC; ++c) acc[c] = 0.f;

    const float* hp = hs + (size_t)row * NH;

    for (int half = 0; half < 2; ++half) {
        __syncthreads();
        for (int i = tid; i < 256 * NC; i += 256) Wsm[i] = W[half * 256 * NC + i];
        __syncthreads();
        const float* hph = hp + half * 256;
        for (int h = 0; h < 256; h += 4) {
            float4 x = *(const float4*)(hph + h);
#pragma unroll
            for (int j = 0; j < 4; ++j) {
                const float a = (&x.x)[j];
                const float4* wr = (const float4*)(&Wsm[(h + j) * NC]);
#pragma unroll
                for (int q = 0; q < 6; ++q) {
                    float4 wv = wr[q];
                    acc[q * 4 + 0] = fmaf(a, wv.x, acc[q * 4 + 0]);
                    acc[q * 4 + 1] = fmaf(a, wv.y, acc[q * 4 + 1]);
                    acc[q * 4 + 2] = fmaf(a, wv.z, acc[q * 4 + 2]);
                    acc[q * 4 + 3] = fmaf(a, wv.w, acc[q * 4 + 3]);
                }
            }
        }
    }

    const int b = row / NT;
    const int t = row % NT;
#pragma unroll
    for (int c = 0; c < NC; ++c)
        g_scores[((size_t)(b * NC + c)) * NT + t] = acc[c] + bsm[c];
}

// ---------------------------------------------------------------------------
// Kernel 2: per-(b,c) inclusive prefix -> g_cum[b][c][1..T], g_cum[..][0]=0.
// ---------------------------------------------------------------------------
__global__ __launch_bounds__(32) void cumsum_kernel() {
    const int bc = blockIdx.x;                      // 0..191
    const int lane = threadIdx.x;
    const float* sp = g_scores + (size_t)bc * NT;
    float* cp = g_cum + (size_t)bc * (NT + 1);
    if (lane == 0) cp[0] = 0.f;
    float carry = 0.f;
#pragma unroll 2
    for (int base = 0; base < NT; base += 32) {
        float v = sp[base + lane];
#pragma unroll
        for (int off = 1; off < 32; off <<= 1) {
            float n = __shfl_up_sync(FULL, v, off);
            if (lane >= off) v += n;
        }
        cp[base + lane + 1] = carry + v;
        carry += __shfl_sync(FULL, v, 31);
    }
}

// ---------------------------------------------------------------------------
// Kernel 3: 6-warp scan, 4 channels/warp, 8 lanes/channel.
// Same math as R11 (passed, rel_err 7.6e-6). Scheduling changes only:
//  - 8-step outer loop NOT unrolled (I$-friendly body ~8KB)
//  - split barrier: bar.arrive -> tail partial -> bar.sync (overlap skew)
//  - ring E[t] written by ALL lanes (own-store visibility pre-sync)
//  - float4 vectorized pow-2 re-anchor every 8 steps
//  - cum staged via small smem table (no dynamic register arrays)
// ---------------------------------------------------------------------------
__global__ __launch_bounds__(192) void scan_kernel(const float* __restrict__ trans,
                                                   const float* __restrict__ dur,
                                                   const int* __restrict__ lengths,
                                                   float* __restrict__ out) {
    __shared__ __align__(16) float ring[NC * RST];   // ~25.3 KB
    __shared__ float u_sm[2][NC];
    __shared__ float cum_sm[NC][34];                 // 33 used (+1 pad)

    const int tid = threadIdx.x;
    const int warp = tid >> 5;
    const int lane = tid & 31;
    const int grp = lane >> 3;         // channel group within warp (0..3)
    const int sl = lane & 7;           // sub-lane within group
    const int c = warp * 4 + grp;      // this lane's channel
    const int b = blockIdx.x;
    const float LN2 = 0.6931471805599453f;

    for (int i = tid; i < NC * RST; i += 192) {
        const int x = i % RST;
        ring[i] = (x == 0 || x == 128) ? 1.f : 0.f;
    }

    // Constants.
    const float ed1s = __expf(dur[0 * NC + c]);          // k = 1
    float edt[13];
#pragma unroll
    for (int i = 0; i < 13; ++i) {
        const int k = 2 + 13 * sl + i;
        edt[i] = (k <= NK) ? __expf(dur[(k - 1) * NC + c]) : 0.f;
    }
    const float etr0 = __expf(trans[(3 * sl + 0) * NC + c]);
    const float etr1 = __expf(trans[(3 * sl + 1) * NC + c]);
    const float etr2 = __expf(trans[(3 * sl + 2) * NC + c]);
    __syncthreads();

    int len = lengths[b];
    len = len < 1 ? 1 : (len > NT ? NT : len);

    const float* cumb = g_cum + (size_t)(b * NC + c) * (NT + 1);
    float* ringc = ring + c * RST;

    float R = 0.f, shift = 0.f, tailD = 0.f, Et1 = 1.f;
    float beta = __expf(cumb[1]);
    float rbeta = __expf(-cumb[1]);

#pragma unroll 1
    for (int t8 = 1; t8 <= NT; t8 += 8) {
        const int base = (t8 - 1) & 31;
        if (base == 0) {
            // Stage cum[t8+1 .. t8+33] for this channel (33 values).
            for (int j = sl; j < 33; j += 8) {
                int idx = t8 + 1 + j;
                idx = idx > NT ? NT : idx;
                cum_sm[c][j] = cumb[idx];
            }
            __syncwarp();
        }
        if (t8 > 1) {
            __syncwarp();
            // ---- group-local re-anchor: Et1 -> ~2^{-45} (exact pow-2) ----
            int eb = (__float_as_int(Et1) >> 23) & 255;
            if (eb == 0) eb = 1;
            int de = eb - 82;
            de = de < -100 ? -100 : (de > 120 ? 120 : de);
            const float sc = __int_as_float((127 - de) << 23);   // 2^{-de}
            const float rsc = __int_as_float((127 + de) << 23);  // 2^{+de}
            float4* r4 = (float4*)ringc;
#pragma unroll
            for (int m = 0; m < 8; ++m) {
                float4 v = r4[8 * m + sl];
                v.x *= sc; v.y *= sc; v.z *= sc; v.w *= sc;
                r4[8 * m + sl] = v;
            }
            Et1 *= sc;
            tailD *= sc;
            R += (float)de * LN2;
            beta *= rsc;
            rbeta *= sc;
            __syncwarp();
        }

#pragma unroll
        for (int q = 0; q < 8; ++q) {
            const int t = t8 + q;
            const int par = (q + 1) & 1;          // t8 is always odd

            const float D = fmaf(Et1, ed1s, tailD);
            const float u = D * beta;             // exp(alpha_c - shift)
            if (sl == 0) u_sm[par][c] = u;
            asm volatile("bar.arrive 1, 384;" ::: "memory");

            // Tail partial for t+1 (independent of u_sm; overlaps barrier).
            const float* p = ringc + (((t - 1 - 13 * sl) & 127) + 116);
            float ta = p[12] * edt[0];
            float tb2 = p[11] * edt[1];
            float tc = p[10] * edt[2];
            ta = fmaf(p[9], edt[3], ta);
            tb2 = fmaf(p[8], edt[4], tb2);
            tc = fmaf(p[7], edt[5], tc);
            ta = fmaf(p[6], edt[6], ta);
            tb2 = fmaf(p[5], edt[7], tb2);
            tc = fmaf(p[4], edt[8], tc);
            ta = fmaf(p[3], edt[9], ta);
            tb2 = fmaf(p[2], edt[10], tb2);
            tc = fmaf(p[1], edt[11], tc);
            ta = fmaf(p[0], edt[12], ta);
            float tb = ta + tb2 + tc;

            const float crN = cum_sm[c][base + q + 1] + R;   // cum[t+1] + R

            asm volatile("bar.sync 1, 384;" ::: "memory");

            const float* ub = u_sm[par];
            const float uv0 = ub[3 * sl + 0];
            const float uv1 = ub[3 * sl + 1];
            const float uv2 = ub[3 * sl + 2];
            float w = fmaf(uv2, etr2, fmaf(uv1, etr1, uv0 * etr0));

            // 3-round group butterflies, interleaved.
#pragma unroll
            for (int off = 4; off > 0; off >>= 1) {
                w  += __shfl_xor_sync(FULL, w, off);
                tb += __shfl_xor_sync(FULL, tb, off);
            }

            const float Et = w * rbeta;           // E[t]
            const int slot = t & 127;
            ringc[slot] = Et;                     // all lanes: own-store
            ringc[slot + 128] = Et;

            if (t == len) {
                float su = uv0 + uv1 + uv2;
#pragma unroll
                for (int off = 4; off > 0; off >>= 1)
                    su += __shfl_xor_sync(FULL, su, off);
                if (tid == 0) out[b] = shift + __logf(fmaxf(su, 1e-37f));
            }

            // shift feedback (uniform across warps; pure ALU).
            const float u0 = __shfl_sync(FULL, uv0, 0);
            int e0 = (__float_as_int(u0) >> 23) & 255;
            int ds = (e0 == 0) ? -30 : (e0 - 127);
            ds = ds < -30 ? -30 : (ds > 30 ? 30 : ds);
            shift = fmaf((float)ds, LN2, shift);

            const float xn = crN - shift;
            beta = __expf(xn);
            rbeta = __expf(-xn);

            Et1 = Et;
            tailD = tb;
        }
        if (t8 + 7 >= len) break;
    }
}

// ---------------------------------------------------------------------------
extern "C" void kernel_launch(void* const* d_in, const int* in_sizes, int n_in,
                              void* d_out, int out_size) {
    const float* hs    = (const float*)d_in[0];   // [B,T,H]
    const float* W     = (const float*)d_in[1];   // [H,C]
    const float* bias  = (const float*)d_in[2];   // [C]
    const float* trans = (const float*)d_in[3];   // [C,C]
    const float* dur   = (const float*)d_in[4];   // [K,C]
    const int*   len   = (const int*)d_in[5];     // [B]
    float* out = (float*)d_out;

    gemm_kernel<<<(NB * NT) / 256, 256>>>(hs, W, bias);
    cumsum_kernel<<<NB * NC, 32>>>();
    scan_kernel<<<NB, 192>>>(trans, dur, len, out);
}